// round 10
// baseline (speedup 1.0000x reference)
#include <cuda_runtime.h>
#include <cstdint>

// Problem constants (fixed by setup_inputs): B=4, N=512, K=27
#define BB 4
#define NN 512
#define KK 27
#define S_ELEMS 28311552u          // B*N*N*K
#define NCHUNK 262144u             // S / 108 — one aligned t-quad per thread
#define TPB 256u

// Output layout (concatenated, reference return order):
//   [0, S)        distances    [B,N,N,K]
//   [S, 4S)       distance_vec [B,N,N,K,3]
//   [4S, 5S)      mask (1.0/0.0) [B,N,N,K]
//   [5S, 5S+324)  offset_cart  [B,K,3]

__device__ __forceinline__ void offset_for(const float* __restrict__ cell,
                                           unsigned b, unsigned k,
                                           float& ox, float& oy, float& oz) {
    const float f0 = (float)((int)(k / 9u) - 1);
    const float f1 = (float)((int)((k / 3u) % 3u) - 1);
    const float f2 = (float)((int)(k % 3u) - 1);
    const float* c = cell + b * 9u;
    // match jnp rounding: left-to-right adds, no fma
    ox = __fadd_rn(__fadd_rn(__fmul_rn(f0, __ldg(c + 0)), __fmul_rn(f1, __ldg(c + 3))),
                   __fmul_rn(f2, __ldg(c + 6)));
    oy = __fadd_rn(__fadd_rn(__fmul_rn(f0, __ldg(c + 1)), __fmul_rn(f1, __ldg(c + 4))),
                   __fmul_rn(f2, __ldg(c + 7)));
    oz = __fadd_rn(__fadd_rn(__fmul_rn(f0, __ldg(c + 2)), __fmul_rn(f1, __ldg(c + 5))),
                   __fmul_rn(f2, __ldg(c + 8)));
}

// Load (pj, pi, b) for pair-index t.
__device__ __forceinline__ void load_pair(const float* __restrict__ pos, unsigned t,
                                          unsigned& b,
                                          float& pjx, float& pjy, float& pjz,
                                          float& pix, float& piy, float& piz) {
    const unsigned j = t & (NN - 1);
    const unsigned i = (t >> 9) & (NN - 1);
    b = t >> 18;
    const float* pj = pos + ((size_t)b * NN + j) * 3u;
    const float* pi = pos + ((size_t)b * NN + i) * 3u;
    pjx = __ldg(pj + 0); pjy = __ldg(pj + 1); pjz = __ldg(pj + 2);
    pix = __ldg(pi + 0); piy = __ldg(pi + 1); piz = __ldg(pi + 2);
}

__global__ __launch_bounds__(TPB)
void pbc_edges_kernel(const float* __restrict__ pos,
                      const float* __restrict__ cell,
                      float* __restrict__ out) {
    // Scalar 3-float offset table (R5-proven broadcast-friendly layout).
    __shared__ float s_off[BB * KK * 3];
    if (threadIdx.x < BB * KK) {
        const unsigned b = threadIdx.x / KK;
        const unsigned k = threadIdx.x % KK;
        float ox, oy, oz;
        offset_for(cell, b, k, ox, oy, oz);
        s_off[threadIdx.x * 3 + 0] = ox;
        s_off[threadIdx.x * 3 + 1] = oy;
        s_off[threadIdx.x * 3 + 2] = oz;
        if (blockIdx.x == 0) {  // fused offset_cart tail
            float* dst = out + 5ull * S_ELEMS + (size_t)threadIdx.x * 3u;
            dst[0] = ox; dst[1] = oy; dst[2] = oz;
        }
    }
    __syncthreads();

    const unsigned q = blockIdx.x * TPB + threadIdx.x;   // [0, 262144)
    const unsigned tq = q * 4u;                          // first pair index
    const size_t ebase = (size_t)tq * KK;                // first element = 108*q

    // Current pair's positions (loaded once per t, warp-uniform schedule).
    unsigned cb;
    float cjx, cjy, cjz, cix, ciy, ciz;
    load_pair(pos, tq, cb, cjx, cjy, cjz, cix, ciy, ciz);
    const float* obase = s_off + cb * (KK * 3);

#pragma unroll
    for (int g = 0; g < 27; ++g) {
        // Group g covers elements 4g..4g+3; k = (4g+e)%27, t advances when
        // (4g+e)/27 increments — all compile-time after unroll (no divergence).
        const int tl_lo = (4 * g) / 27;
        const int tl_hi = (4 * g + 3) / 27;
        const bool straddle = (tl_hi != tl_lo);

        unsigned nb = cb;
        float njx = cjx, njy = cjy, njz = cjz, nix = cix, niy = ciy, niz = ciz;
        const float* nobase = obase;
        if (straddle) {
            load_pair(pos, tq + (unsigned)tl_hi, nb, njx, njy, njz, nix, niy, niz);
            nobase = s_off + nb * (KK * 3);
        }

        float d[4], mf[4], vxm[4], vym[4], vzm[4];

#pragma unroll
        for (int e = 0; e < 4; ++e) {
            const int k = (4 * g + e) % 27;              // literal after unroll
            const bool hi = ((4 * g + e) / 27) != tl_lo; // literal after unroll

            const float pjx = hi ? njx : cjx;
            const float pjy = hi ? njy : cjy;
            const float pjz = hi ? njz : cjz;
            const float pix = hi ? nix : cix;
            const float piy = hi ? niy : ciy;
            const float piz = hi ? niz : ciz;
            const float* ob = hi ? nobase : obase;

            const float ox = ob[3 * k + 0];
            const float oy = ob[3 * k + 1];
            const float oz = ob[3 * k + 2];

            // vec = (pos_j + offset) - pos_i  (reference add order, no fma)
            const float vx = __fadd_rn(__fadd_rn(pjx, ox), -pix);
            const float vy = __fadd_rn(__fadd_rn(pjy, oy), -piy);
            const float vz = __fadd_rn(__fadd_rn(pjz, oz), -piz);

            const float sq = __fadd_rn(__fadd_rn(__fmul_rn(vx, vx), __fmul_rn(vy, vy)),
                                       __fmul_rn(vz, vz));

            const bool m = (sq > 1e-8f) & (sq <= 25.0f);
            mf[e] = m ? 1.0f : 0.0f;
            d[e]  = m ? __fsqrt_rn(sq) : 0.0f;
            vxm[e] = m ? vx : 0.0f;
            vym[e] = m ? vy : 0.0f;
            vzm[e] = m ? vz : 0.0f;
        }

        const size_t idx0 = ebase + (size_t)(4 * g);

        // Aligned 128-bit streaming stores (108*q*4B and offsets all ≡0 mod 16).
        __stcs((float4*)(out + idx0), make_float4(d[0], d[1], d[2], d[3]));
        __stcs((float4*)(out + 4ull * S_ELEMS + idx0),
               make_float4(mf[0], mf[1], mf[2], mf[3]));

        float4* vec4 = (float4*)(out + (size_t)S_ELEMS + idx0 * 3u);
        __stcs(vec4 + 0, make_float4(vxm[0], vym[0], vzm[0], vxm[1]));
        __stcs(vec4 + 1, make_float4(vym[1], vzm[1], vxm[2], vym[2]));
        __stcs(vec4 + 2, make_float4(vzm[2], vxm[3], vym[3], vzm[3]));

        if (straddle) {  // promote next pair to current (register renames)
            cb = nb; obase = nobase;
            cjx = njx; cjy = njy; cjz = njz;
            cix = nix; ciy = niy; ciz = niz;
        }
    }
}

extern "C" void kernel_launch(void* const* d_in, const int* in_sizes, int n_in,
                              void* d_out, int out_size) {
    const float* pos  = (const float*)d_in[0];   // [B,N,3]
    const float* cell = (const float*)d_in[1];   // [B,3,3]
    float* out = (float*)d_out;

    pbc_edges_kernel<<<NCHUNK / TPB, TPB>>>(pos, cell, out);  // 1024 blocks
}

// round 13
// speedup vs baseline: 6.9746x; 6.9746x over previous
#include <cuda_runtime.h>
#include <cstdint>

// Problem constants (fixed by setup_inputs): B=4, N=512, K=27
#define BB 4
#define NN 512
#define KK 27
#define S_ELEMS 28311552u          // B*N*N*K
#define GROUPS (S_ELEMS / 4u)      // 7,077,888 = 27648 * 256 exactly
#define TPB 256u

// Output layout (concatenated, reference return order):
//   [0, S)        distances    [B,N,N,K]
//   [S, 4S)       distance_vec [B,N,N,K,3]
//   [4S, 5S)      mask (1.0/0.0) [B,N,N,K]
//   [5S, 5S+324)  offset_cart  [B,K,3]

__device__ __forceinline__ void offset_for(const float* __restrict__ cell,
                                           unsigned b, unsigned k,
                                           float& ox, float& oy, float& oz) {
    const float f0 = (float)((int)(k / 9u) - 1);
    const float f1 = (float)((int)((k / 3u) % 3u) - 1);
    const float f2 = (float)((int)(k % 3u) - 1);
    const float* c = cell + b * 9u;
    // match jnp rounding: left-to-right adds, no fma
    ox = __fadd_rn(__fadd_rn(__fmul_rn(f0, __ldg(c + 0)), __fmul_rn(f1, __ldg(c + 3))),
                   __fmul_rn(f2, __ldg(c + 6)));
    oy = __fadd_rn(__fadd_rn(__fmul_rn(f0, __ldg(c + 1)), __fmul_rn(f1, __ldg(c + 4))),
                   __fmul_rn(f2, __ldg(c + 7)));
    oz = __fadd_rn(__fadd_rn(__fmul_rn(f0, __ldg(c + 2)), __fmul_rn(f1, __ldg(c + 5))),
                   __fmul_rn(f2, __ldg(c + 8)));
}

__global__ __launch_bounds__(TPB)
void pbc_edges_kernel(const float* __restrict__ pos,
                      const float* __restrict__ cell,
                      float* __restrict__ out) {
    // Scalar 3-float offset table (R5-proven broadcast-friendly layout).
    __shared__ float s_off[BB * KK * 3];
    if (threadIdx.x < BB * KK) {
        const unsigned b = threadIdx.x / KK;
        const unsigned k = threadIdx.x % KK;
        float ox, oy, oz;
        offset_for(cell, b, k, ox, oy, oz);
        s_off[threadIdx.x * 3 + 0] = ox;
        s_off[threadIdx.x * 3 + 1] = oy;
        s_off[threadIdx.x * 3 + 2] = oz;
        // Fused offset_cart output: block 0 writes the tiny [B,K,3] tail.
        if (blockIdx.x == 0) {
            float* dst = out + 5ull * S_ELEMS + (size_t)threadIdx.x * 3u;
            dst[0] = ox;
            dst[1] = oy;
            dst[2] = oz;
        }
    }
    __syncthreads();

    const unsigned g = blockIdx.x * TPB + threadIdx.x;
    if (g >= GROUPS) return;
    const unsigned base = g * 4u;     // 4 consecutive elements -> lane-contiguous stores

    // Decompose base once; carry (k, t) incrementally across the 4 elements.
    unsigned k = base % KK;            // single magic multiply
    unsigned t = base / KK;

    // ONE set of position registers; loaded at e=0, reloaded in place only
    // when k wraps (data-dependent, ~1/27 of lanes per iteration).
    unsigned b = t >> 18;
    const unsigned j0 = t & (NN - 1);
    const unsigned i0 = (t >> 9) & (NN - 1);
    const float* pjp = pos + ((size_t)b * NN + j0) * 3u;
    const float* pip = pos + ((size_t)b * NN + i0) * 3u;
    float pjx = __ldg(pjp + 0), pjy = __ldg(pjp + 1), pjz = __ldg(pjp + 2);
    float pix = __ldg(pip + 0), piy = __ldg(pip + 1), piz = __ldg(pip + 2);

    float d[4], mf[4], vxm[4], vym[4], vzm[4];

#pragma unroll
    for (int e = 0; e < 4; ++e) {
        const float* off = s_off + (b * KK + k) * 3u;
        const float ox = off[0], oy = off[1], oz = off[2];

        // vec = (pos_j + offset) - pos_i  (reference add order, no fma)
        const float vx = __fadd_rn(__fadd_rn(pjx, ox), -pix);
        const float vy = __fadd_rn(__fadd_rn(pjy, oy), -piy);
        const float vz = __fadd_rn(__fadd_rn(pjz, oz), -piz);

        const float sq = __fadd_rn(__fadd_rn(__fmul_rn(vx, vx), __fmul_rn(vy, vy)),
                                   __fmul_rn(vz, vz));

        const bool m = (sq > 1e-8f) & (sq <= 25.0f);
        mf[e] = m ? 1.0f : 0.0f;
        d[e]  = m ? __fsqrt_rn(sq) : 0.0f;
        vxm[e] = m ? vx : 0.0f;
        vym[e] = m ? vy : 0.0f;
        vzm[e] = m ? vz : 0.0f;

        // advance; on wrap, reload the SAME registers for the new t
        ++k;
        if (e < 3 && k == KK) {
            k = 0;
            ++t;
            const unsigned j = t & (NN - 1);
            const unsigned i = (t >> 9) & (NN - 1);
            b = t >> 18;
            const float* pj2 = pos + ((size_t)b * NN + j) * 3u;
            const float* pi2 = pos + ((size_t)b * NN + i) * 3u;
            pjx = __ldg(pj2 + 0); pjy = __ldg(pj2 + 1); pjz = __ldg(pj2 + 2);
            pix = __ldg(pi2 + 0); piy = __ldg(pi2 + 1); piz = __ldg(pi2 + 2);
        }
    }

    // Fully coalesced 128-bit streaming stores.
    float4* dist4 = (float4*)(out + base);
    __stcs(dist4, make_float4(d[0], d[1], d[2], d[3]));

    float4* mask4 = (float4*)(out + 4ull * S_ELEMS + base);
    __stcs(mask4, make_float4(mf[0], mf[1], mf[2], mf[3]));

    // distance_vec: 12 contiguous floats per thread, base*3 is 4-aligned.
    float4* vec4 = (float4*)(out + (size_t)S_ELEMS + (size_t)base * 3u);
    __stcs(vec4 + 0, make_float4(vxm[0], vym[0], vzm[0], vxm[1]));
    __stcs(vec4 + 1, make_float4(vym[1], vzm[1], vxm[2], vym[2]));
    __stcs(vec4 + 2, make_float4(vzm[2], vxm[3], vym[3], vzm[3]));
}

extern "C" void kernel_launch(void* const* d_in, const int* in_sizes, int n_in,
                              void* d_out, int out_size) {
    const float* pos  = (const float*)d_in[0];   // [B,N,3]
    const float* cell = (const float*)d_in[1];   // [B,3,3]
    float* out = (float*)d_out;

    const unsigned blocks = GROUPS / TPB;        // exact: 27648
    pbc_edges_kernel<<<blocks, TPB>>>(pos, cell, out);
}